// round 2
// baseline (speedup 1.0000x reference)
#include <cuda_runtime.h>
#include <math.h>

#define T_MAX 2048
#define B_SZ  16
#define D_SZ  1024
#define N_SZ  64
#define M_ROWS (T_MAX * B_SZ)   // 32768

// proj row m = t*16+b: [0:64)=k_norm, [64:128)=v, [128:192)=q, [192:256)=sigmoid(beta)
// +32 padded rows (zero-init) so the scan's 2-step-ahead prefetch stays in bounds.
__device__ __align__(16) float g_proj[(M_ROWS + 32) * 256];

// ---- packed fp32x2 helpers (full-rate fp32 on sm_103a) ----
__device__ __forceinline__ unsigned long long pk2(float x, float y) {
    unsigned long long r;
    asm("mov.b64 %0, {%1, %2};" : "=l"(r) : "f"(x), "f"(y));
    return r;
}
__device__ __forceinline__ void fma2(unsigned long long& d, unsigned long long a, unsigned long long b) {
    asm("fma.rn.f32x2 %0, %1, %2, %0;" : "+l"(d) : "l"(a), "l"(b));
}
__device__ __forceinline__ float2 unpk2(unsigned long long v) {
    float2 f;
    asm("mov.b64 {%0, %1}, %2;" : "=f"(f.x), "=f"(f.y) : "l"(v));
    return f;
}

// ---- Kernel 1: fused projection GEMM ----
__global__ __launch_bounds__(256, 2)
void proj_gemm(const float* __restrict__ x,
               const float* __restrict__ Wk, const float* __restrict__ Wv,
               const float* __restrict__ Wq, const float* __restrict__ Wb)
{
    constexpr int BM = 128, BK = 16;
    __shared__ __align__(16) float As[BK][BM];   // transposed A tile
    __shared__ __align__(16) float Bs[BK][128];

    const int tid  = threadIdx.x;
    const int row0 = blockIdx.x * BM;
    const int bn   = blockIdx.y;            // 0: cols [0,128)=k|v, 1: [128,256)=q|beta

    const int a_r = tid >> 2;                // 0..63
    const int a_c = (tid & 3) * 4;           // 0,4,8,12
    const float* xA0 = x + (size_t)(row0 + a_r) * D_SZ + a_c;
    const float* xA1 = x + (size_t)(row0 + a_r + 64) * D_SZ + a_c;

    const int nl   = tid & 127;
    const int ncol = bn * 128 + nl;
    const float* Wm = (ncol < 64) ? Wk : (ncol < 128) ? Wv : (ncol < 192) ? Wq : Wb;
    const int b_c  = (tid >> 7) * 8;
    const float* wB = Wm + (size_t)(ncol & 63) * D_SZ + b_c;

    const int ty = tid >> 4;                 // 8 rows each
    const int tx = tid & 15;                 // 8 cols each

    unsigned long long acc[4][8];
    #pragma unroll
    for (int p = 0; p < 4; p++)
        #pragma unroll
        for (int j = 0; j < 8; j++) acc[p][j] = 0ULL;

    float4 ra0 = *(const float4*)(xA0);
    float4 ra1 = *(const float4*)(xA1);
    float4 rb0 = *(const float4*)(wB);
    float4 rb1 = *(const float4*)(wB + 4);

    for (int kt = 0; kt < D_SZ; kt += BK) {
        __syncthreads();
        As[a_c + 0][a_r] = ra0.x; As[a_c + 1][a_r] = ra0.y;
        As[a_c + 2][a_r] = ra0.z; As[a_c + 3][a_r] = ra0.w;
        As[a_c + 0][a_r + 64] = ra1.x; As[a_c + 1][a_r + 64] = ra1.y;
        As[a_c + 2][a_r + 64] = ra1.z; As[a_c + 3][a_r + 64] = ra1.w;
        Bs[b_c + 0][nl] = rb0.x; Bs[b_c + 1][nl] = rb0.y;
        Bs[b_c + 2][nl] = rb0.z; Bs[b_c + 3][nl] = rb0.w;
        Bs[b_c + 4][nl] = rb1.x; Bs[b_c + 5][nl] = rb1.y;
        Bs[b_c + 6][nl] = rb1.z; Bs[b_c + 7][nl] = rb1.w;
        __syncthreads();

        if (kt + BK < D_SZ) {
            ra0 = *(const float4*)(xA0 + kt + BK);
            ra1 = *(const float4*)(xA1 + kt + BK);
            rb0 = *(const float4*)(wB + kt + BK);
            rb1 = *(const float4*)(wB + kt + BK + 4);
        }

        #pragma unroll
        for (int kk = 0; kk < BK; kk++) {
            ulonglong2 aA = *(const ulonglong2*)&As[kk][ty * 8];
            ulonglong2 aB = *(const ulonglong2*)&As[kk][ty * 8 + 4];
            float4 b0 = *(const float4*)&Bs[kk][tx * 8];
            float4 b1 = *(const float4*)&Bs[kk][tx * 8 + 4];
            unsigned long long bd[8];
            bd[0] = pk2(b0.x, b0.x); bd[1] = pk2(b0.y, b0.y);
            bd[2] = pk2(b0.z, b0.z); bd[3] = pk2(b0.w, b0.w);
            bd[4] = pk2(b1.x, b1.x); bd[5] = pk2(b1.y, b1.y);
            bd[6] = pk2(b1.z, b1.z); bd[7] = pk2(b1.w, b1.w);
            #pragma unroll
            for (int j = 0; j < 8; j++) {
                fma2(acc[0][j], aA.x, bd[j]);
                fma2(acc[1][j], aA.y, bd[j]);
                fma2(acc[2][j], aB.x, bd[j]);
                fma2(acc[3][j], aB.y, bd[j]);
            }
        }
    }

    const size_t cb = (size_t)bn * 128 + tx * 8;
    #pragma unroll
    for (int p = 0; p < 4; p++) {
        float lo[8], hi[8];
        #pragma unroll
        for (int j = 0; j < 8; j++) { float2 f = unpk2(acc[p][j]); lo[j] = f.x; hi[j] = f.y; }
        size_t r = (size_t)(row0 + ty * 8 + 2 * p) * 256 + cb;
        *(float4*)&g_proj[r]           = make_float4(lo[0], lo[1], lo[2], lo[3]);
        *(float4*)&g_proj[r + 4]       = make_float4(lo[4], lo[5], lo[6], lo[7]);
        *(float4*)&g_proj[r + 256]     = make_float4(hi[0], hi[1], hi[2], hi[3]);
        *(float4*)&g_proj[r + 260]     = make_float4(hi[4], hi[5], hi[6], hi[7]);
    }
}

// ---- Kernel 2: preprocess in place ----
__global__ __launch_bounds__(256)
void prep_kernel(const float* __restrict__ b_beta, int M)
{
    int w    = (blockIdx.x * 256 + threadIdx.x) >> 5;
    int lane = threadIdx.x & 31;
    if (w >= M) return;
    float* row = g_proj + (size_t)w * 256;

    float2 k2 = *(float2*)&row[lane * 2];
    float ss = k2.x * k2.x + k2.y * k2.y;
    #pragma unroll
    for (int o = 16; o > 0; o >>= 1) ss += __shfl_xor_sync(0xffffffffu, ss, o);
    float inv = 1.0f / (sqrtf(ss) + 1e-6f);
    k2.x *= inv; k2.y *= inv;
    *(float2*)&row[lane * 2] = k2;

    float2 b2 = *(float2*)&row[192 + lane * 2];
    float2 bb = *(const float2*)&b_beta[lane * 2];
    b2.x = 1.0f / (1.0f + expf(-(b2.x + bb.x)));
    b2.y = 1.0f / (1.0f + expf(-(b2.y + bb.y)));
    *(float2*)&row[192 + lane * 2] = b2;
}

// ---- Kernel 3: recurrence — one warp per (batch, state-row), no barriers ----
__device__ __forceinline__ float tanh_fast(float x) {
    float e = __expf(2.0f * x);               // ~1e-7 abs err; exact at saturation
    return 1.0f - __fdividef(2.0f, e + 1.0f);
}

__global__ __launch_bounds__(256)
void scan_kernel(const float* __restrict__ S0, float* __restrict__ out,
                 int T, long long out_elems)
{
    const int warp = threadIdx.x >> 5;
    const int lane = threadIdx.x & 31;
    const int gr = blockIdx.x * 8 + warp;    // 0..1023
    const int b  = gr >> 6;
    const int i  = gr & 63;
    const int j0 = lane * 2;

    float2 s = *(const float2*)&S0[(size_t)b * 4096 + i * 64 + j0];

    const float* p = g_proj + (size_t)b * 256;
    float2 kn = __ldg((const float2*)&p[j0]);
    float2 q  = __ldg((const float2*)&p[128 + j0]);
    float  v  = __ldg(&p[64 + i]);
    float  bet= __ldg(&p[192 + i]);
    const float* pn = p + 4096;
    float2 kn_n = __ldg((const float2*)&pn[j0]);
    float2 q_n  = __ldg((const float2*)&pn[128 + j0]);
    float  v_n  = __ldg(&pn[64 + i]);
    float  bet_n= __ldg(&pn[192 + i]);
    const float* pf = pn + 4096;

    float rp  = s.x * kn.x + s.y * kn.y;     // partial retrieved, t=0
    float sqp = 0.0f;                        // partial Sq of t-1

    const bool hasOut = ((long long)T * 1024 <= out_elems);
    const bool hasS   = ((long long)T * 1024 + (long long)B_SZ * 4096 <= out_elems);

    for (int t = 0; t < T; t++) {
        #pragma unroll
        for (int o = 16; o > 0; o >>= 1) {   // dual reduce: rp critical, sqp rides along
            rp  += __shfl_xor_sync(0xffffffffu, rp,  o);
            sqp += __shfl_xor_sync(0xffffffffu, sqp, o);
        }
        if (t > 0 && lane == 0 && hasOut) {
            float sg = __fdividef(1.0f, 1.0f + __expf(-sqp));
            out[(size_t)(t - 1) * 1024 + b * 64 + i] = sqp * sqp * sg;
        }
        float delta = v - rp;
        s.x = tanh_fast(fmaf(bet, s.x, delta * kn.x));
        s.y = tanh_fast(fmaf(bet, s.y, delta * kn.y));
        sqp = s.x * q.x + s.y * q.y;

        kn = kn_n; q = q_n; v = v_n; bet = bet_n;
        kn_n = __ldg((const float2*)&pf[j0]);
        q_n  = __ldg((const float2*)&pf[128 + j0]);
        v_n  = __ldg(&pf[64 + i]);
        bet_n= __ldg(&pf[192 + i]);
        pf += 4096;

        rp = s.x * kn.x + s.y * kn.y;        // partial retrieved, t+1
    }

    #pragma unroll
    for (int o = 16; o > 0; o >>= 1) sqp += __shfl_xor_sync(0xffffffffu, sqp, o);
    if (lane == 0 && hasOut) {
        float sg = __fdividef(1.0f, 1.0f + __expf(-sqp));
        out[(size_t)(T - 1) * 1024 + b * 64 + i] = sqp * sqp * sg;
    }
    if (hasS)
        *(float2*)&out[(size_t)T * 1024 + (size_t)b * 4096 + i * 64 + j0] = s;
}

// ---- host launcher ----
extern "C" void kernel_launch(void* const* d_in, const int* in_sizes, int n_in,
                              void* d_out, int out_size)
{
    const float* x  = (const float*)d_in[0];
    const float* S0 = (const float*)d_in[1];
    const float* Wk = (const float*)d_in[2];
    const float* Wv = (const float*)d_in[3];
    const float* Wq = (const float*)d_in[4];
    const float* Wb = (const float*)d_in[5];
    const float* bb = (const float*)d_in[6];

    dim3 g(M_ROWS / 128, 2);
    proj_gemm<<<g, 256>>>(x, Wk, Wv, Wq, Wb);
    prep_kernel<<<M_ROWS / 8, 256>>>(bb, M_ROWS);        // 8 warps/block, 1 row/warp
    scan_kernel<<<128, 256>>>(S0, (float*)d_out, T_MAX, (long long)out_size);
}

// round 4
// speedup vs baseline: 1.2838x; 1.2838x over previous
#include <cuda_runtime.h>
#include <math.h>

#define T_MAX 2048
#define B_SZ  16
#define D_SZ  1024
#define N_SZ  64
#define M_ROWS (T_MAX * B_SZ)   // 32768

// proj row m = t*16+b: [0:64)=k_norm, [64:128)=v, [128:192)=q, [192:256)=sigmoid(beta)
// +64 padded rows (zero-init) so the scan's 4-step-ahead prefetch stays in bounds.
__device__ __align__(16) float g_proj[(M_ROWS + 64) * 256];

// ---- packed fp32x2 helpers ----
__device__ __forceinline__ unsigned long long pk2(float x, float y) {
    unsigned long long r;
    asm("mov.b64 %0, {%1, %2};" : "=l"(r) : "f"(x), "f"(y));
    return r;
}
__device__ __forceinline__ void fma2(unsigned long long& d, unsigned long long a, unsigned long long b) {
    asm("fma.rn.f32x2 %0, %1, %2, %0;" : "+l"(d) : "l"(a), "l"(b));
}
__device__ __forceinline__ float2 unpk2(unsigned long long v) {
    float2 f;
    asm("mov.b64 {%0, %1}, %2;" : "=f"(f.x), "=f"(f.y) : "l"(v));
    return f;
}
__device__ __forceinline__ float dot4(float4 a, float4 b) {
    return fmaf(a.x, b.x, a.y * b.y) + fmaf(a.z, b.z, a.w * b.w);
}

// ---- Kernel 1: fused projection GEMM (wavefront-minimal shared fragments) ----
__global__ __launch_bounds__(256, 2)
void proj_gemm(const float* __restrict__ x,
               const float* __restrict__ Wk, const float* __restrict__ Wv,
               const float* __restrict__ Wq, const float* __restrict__ Wb)
{
    constexpr int BM = 128, BK = 16, LDA = 132;  // 528B rows: 16B-aligned for LDS.128
    __shared__ __align__(16) float As[BK][LDA];  // transposed A tile
    __shared__ __align__(16) float Bs[BK][128];

    const int tid  = threadIdx.x;
    const int row0 = blockIdx.x * BM;
    const int bn   = blockIdx.y;            // 0: cols [0,128)=k|v, 1: [128,256)=q|beta

    const int a_r = tid >> 2;                // 0..63
    const int a_c = (tid & 3) * 4;           // 0,4,8,12
    const float* xA0 = x + (size_t)(row0 + a_r) * D_SZ + a_c;
    const float* xA1 = x + (size_t)(row0 + a_r + 64) * D_SZ + a_c;

    const int nl   = tid & 127;
    const int ncol = bn * 128 + nl;
    const float* Wm = (ncol < 64) ? Wk : (ncol < 128) ? Wv : (ncol < 192) ? Wq : Wb;
    const int b_c  = (tid >> 7) * 8;
    const float* wB = Wm + (size_t)(ncol & 63) * D_SZ + b_c;

    const int ty = tid >> 4;                 // 8 M-rows (4 packed pairs)
    const int tx = tid & 15;                 // cols [tx*4, tx*4+4) and [64+tx*4, ...)

    unsigned long long acc[4][8];
    #pragma unroll
    for (int p = 0; p < 4; p++)
        #pragma unroll
        for (int j = 0; j < 8; j++) acc[p][j] = 0ULL;

    float4 ra0 = *(const float4*)(xA0);
    float4 ra1 = *(const float4*)(xA1);
    float4 rb0 = *(const float4*)(wB);
    float4 rb1 = *(const float4*)(wB + 4);

    for (int kt = 0; kt < D_SZ; kt += BK) {
        __syncthreads();
        As[a_c + 0][a_r] = ra0.x; As[a_c + 1][a_r] = ra0.y;
        As[a_c + 2][a_r] = ra0.z; As[a_c + 3][a_r] = ra0.w;
        As[a_c + 0][a_r + 64] = ra1.x; As[a_c + 1][a_r + 64] = ra1.y;
        As[a_c + 2][a_r + 64] = ra1.z; As[a_c + 3][a_r + 64] = ra1.w;
        Bs[b_c + 0][nl] = rb0.x; Bs[b_c + 1][nl] = rb0.y;
        Bs[b_c + 2][nl] = rb0.z; Bs[b_c + 3][nl] = rb0.w;
        Bs[b_c + 4][nl] = rb1.x; Bs[b_c + 5][nl] = rb1.y;
        Bs[b_c + 6][nl] = rb1.z; Bs[b_c + 7][nl] = rb1.w;
        __syncthreads();

        if (kt + BK < D_SZ) {
            ra0 = *(const float4*)(xA0 + kt + BK);
            ra1 = *(const float4*)(xA1 + kt + BK);
            rb0 = *(const float4*)(wB + kt + BK);
            rb1 = *(const float4*)(wB + kt + BK + 4);
        }

        #pragma unroll
        for (int kk = 0; kk < BK; kk++) {
            ulonglong2 aA = *(const ulonglong2*)&As[kk][ty * 8];      // row pairs (0,1),(2,3)
            ulonglong2 aB = *(const ulonglong2*)&As[kk][ty * 8 + 4];  // row pairs (4,5),(6,7)
            float4 b0 = *(const float4*)&Bs[kk][tx * 4];              // 16B-contiguous
            float4 b1 = *(const float4*)&Bs[kk][64 + tx * 4];
            unsigned long long bd[8];
            bd[0] = pk2(b0.x, b0.x); bd[1] = pk2(b0.y, b0.y);
            bd[2] = pk2(b0.z, b0.z); bd[3] = pk2(b0.w, b0.w);
            bd[4] = pk2(b1.x, b1.x); bd[5] = pk2(b1.y, b1.y);
            bd[6] = pk2(b1.z, b1.z); bd[7] = pk2(b1.w, b1.w);
            #pragma unroll
            for (int j = 0; j < 8; j++) {
                fma2(acc[0][j], aA.x, bd[j]);
                fma2(acc[1][j], aA.y, bd[j]);
                fma2(acc[2][j], aB.x, bd[j]);
                fma2(acc[3][j], aB.y, bd[j]);
            }
        }
    }

    const size_t c0 = (size_t)bn * 128 + tx * 4;
    #pragma unroll
    for (int p = 0; p < 4; p++) {
        float lo[8], hi[8];
        #pragma unroll
        for (int j = 0; j < 8; j++) { float2 f = unpk2(acc[p][j]); lo[j] = f.x; hi[j] = f.y; }
        size_t r = (size_t)(row0 + ty * 8 + 2 * p) * 256 + c0;
        *(float4*)&g_proj[r]            = make_float4(lo[0], lo[1], lo[2], lo[3]);
        *(float4*)&g_proj[r + 64]       = make_float4(lo[4], lo[5], lo[6], lo[7]);
        *(float4*)&g_proj[r + 256]      = make_float4(hi[0], hi[1], hi[2], hi[3]);
        *(float4*)&g_proj[r + 256 + 64] = make_float4(hi[4], hi[5], hi[6], hi[7]);
    }
}

// ---- Kernel 2: preprocess in place ----
__global__ __launch_bounds__(256)
void prep_kernel(const float* __restrict__ b_beta, int M)
{
    int w    = (blockIdx.x * 256 + threadIdx.x) >> 5;
    int lane = threadIdx.x & 31;
    if (w >= M) return;
    float* row = g_proj + (size_t)w * 256;

    float2 k2 = *(float2*)&row[lane * 2];
    float ss = k2.x * k2.x + k2.y * k2.y;
    #pragma unroll
    for (int o = 16; o > 0; o >>= 1) ss += __shfl_xor_sync(0xffffffffu, ss, o);
    float inv = 1.0f / (sqrtf(ss) + 1e-6f);
    k2.x *= inv; k2.y *= inv;
    *(float2*)&row[lane * 2] = k2;

    float2 b2 = *(float2*)&row[192 + lane * 2];
    float2 bb = *(const float2*)&b_beta[lane * 2];
    b2.x = 1.0f / (1.0f + expf(-(b2.x + bb.x)));
    b2.y = 1.0f / (1.0f + expf(-(b2.y + bb.y)));
    *(float2*)&row[192 + lane * 2] = b2;
}

// ---- Kernel 3: recurrence — 16-lane segments, 2 chains/warp, 4-hop reduce ----
__device__ __forceinline__ float tanh_fast(float x) {
    float e = __expf(2.0f * x);               // ~1e-7 abs err; exact at saturation
    return 1.0f - __fdividef(2.0f, e + 1.0f);
}

__global__ __launch_bounds__(256)
void scan_kernel(const float* __restrict__ S0, float* __restrict__ out,
                 int T, long long out_elems)
{
    const int warp = threadIdx.x >> 5;
    const int lane = threadIdx.x & 31;
    const int half = lane >> 4;              // two 16-lane segments per warp
    const int sl16 = lane & 15;
    const int gr   = (blockIdx.x * 8 + warp) * 2 + half;   // 0..1023
    const int b    = gr >> 6;
    const int i    = gr & 63;
    const int j0   = sl16 * 4;               // my 4 state columns

    float4 s = *(const float4*)&S0[(size_t)b * 4096 + i * 64 + j0];

    // 4-slot input ring, prefetched 4 steps ahead
    const float* p = g_proj + (size_t)b * 256;
    float4 kn[4], q4[4], vk[4];
    float  bt[4];
    #pragma unroll
    for (int s4 = 0; s4 < 4; s4++) {
        const float* ps = p + (size_t)s4 * 4096;
        kn[s4] = __ldg((const float4*)&ps[j0]);
        q4[s4] = __ldg((const float4*)&ps[128 + j0]);
        float vv = __ldg(&ps[64 + i]);
        bt[s4]   = __ldg(&ps[192 + i]);
        vk[s4] = make_float4(vv * kn[s4].x, vv * kn[s4].y, vv * kn[s4].z, vv * kn[s4].w);
    }
    const float* pf = p + (size_t)4 * 4096;

    // arg = beta*s + (v - r)*k = pre - r*k ; pre overlaps the reduce
    float rp = dot4(s, kn[0]);
    float4 pre = make_float4(fmaf(bt[0], s.x, vk[0].x), fmaf(bt[0], s.y, vk[0].y),
                             fmaf(bt[0], s.z, vk[0].z), fmaf(bt[0], s.w, vk[0].w));
    float sqp = 0.0f;

    const bool hasOut = ((long long)T * 1024 <= out_elems);
    const bool hasS   = ((long long)T * 1024 + (long long)B_SZ * 4096 <= out_elems);

    #pragma unroll 4
    for (int t = 0; t < T; t++) {
        const int cu = t & 3, nx = (t + 1) & 3;
        #pragma unroll
        for (int o = 8; o > 0; o >>= 1) {     // 4 hops, stays inside 16-lane segment
            rp  += __shfl_xor_sync(0xffffffffu, rp,  o);
            sqp += __shfl_xor_sync(0xffffffffu, sqp, o);
        }
        s.x = tanh_fast(fmaf(-rp, kn[cu].x, pre.x));
        s.y = tanh_fast(fmaf(-rp, kn[cu].y, pre.y));
        s.z = tanh_fast(fmaf(-rp, kn[cu].z, pre.z));
        s.w = tanh_fast(fmaf(-rp, kn[cu].w, pre.w));
        if (t > 0 && sl16 == 0 && hasOut) {
            float sg = __fdividef(1.0f, 1.0f + __expf(-sqp));
            out[(size_t)(t - 1) * 1024 + b * 64 + i] = sqp * sqp * sg;   // Sq * silu(Sq)
        }
        sqp = dot4(s, q4[cu]);
        rp  = dot4(s, kn[nx]);
        pre = make_float4(fmaf(bt[nx], s.x, vk[nx].x), fmaf(bt[nx], s.y, vk[nx].y),
                          fmaf(bt[nx], s.z, vk[nx].z), fmaf(bt[nx], s.w, vk[nx].w));
        // refill slot cu with step t+4 (padding keeps it in bounds)
        kn[cu] = __ldg((const float4*)&pf[j0]);
        q4[cu] = __ldg((const float4*)&pf[128 + j0]);
        float vv = __ldg(&pf[64 + i]);
        bt[cu]   = __ldg(&pf[192 + i]);
        vk[cu] = make_float4(vv * kn[cu].x, vv * kn[cu].y, vv * kn[cu].z, vv * kn[cu].w);
        pf += 4096;
    }

    #pragma unroll
    for (int o = 8; o > 0; o >>= 1) sqp += __shfl_xor_sync(0xffffffffu, sqp, o);
    if (sl16 == 0 && hasOut) {
        float sg = __fdividef(1.0f, 1.0f + __expf(-sqp));
        out[(size_t)(T - 1) * 1024 + b * 64 + i] = sqp * sqp * sg;
    }
    if (hasS)
        *(float4*)&out[(size_t)T * 1024 + (size_t)b * 4096 + i * 64 + j0] = s;
}

// ---- host launcher ----
extern "C" void kernel_launch(void* const* d_in, const int* in_sizes, int n_in,
                              void* d_out, int out_size)
{
    const float* x  = (const float*)d_in[0];
    const float* S0 = (const float*)d_in[1];
    const float* Wk = (const float*)d_in[2];
    const float* Wv = (const float*)d_in[3];
    const float* Wq = (const float*)d_in[4];
    const float* Wb = (const float*)d_in[5];
    const float* bb = (const float*)d_in[6];

    dim3 g(M_ROWS / 128, 2);
    proj_gemm<<<g, 256>>>(x, Wk, Wv, Wq, Wb);
    prep_kernel<<<M_ROWS / 8, 256>>>(bb, M_ROWS);
    scan_kernel<<<64, 256>>>(S0, (float*)d_out, T_MAX, (long long)out_size);
}

// round 5
// speedup vs baseline: 1.3570x; 1.0570x over previous
#include <cuda_runtime.h>
#include <math.h>

#define T_MAX 2048
#define B_SZ  16
#define D_SZ  1024
#define N_SZ  64
#define M_ROWS (T_MAX * B_SZ)   // 32768

// proj row m = t*16+b: [0:64)=k_norm, [64:128)=v, [128:192)=q, [192:256)=sigmoid(beta)
// +64 padded rows so the scan's 4-step-ahead prefetch stays in bounds.
__device__ __align__(16) float g_proj[(M_ROWS + 64) * 256];

// ---- packed fp32x2 helpers ----
__device__ __forceinline__ unsigned long long pk2(float x, float y) {
    unsigned long long r;
    asm("mov.b64 %0, {%1, %2};" : "=l"(r) : "f"(x), "f"(y));
    return r;
}
__device__ __forceinline__ void fma2(unsigned long long& d, unsigned long long a, unsigned long long b) {
    asm("fma.rn.f32x2 %0, %1, %2, %0;" : "+l"(d) : "l"(a), "l"(b));
}
__device__ __forceinline__ float2 unpk2(unsigned long long v) {
    float2 f;
    asm("mov.b64 {%0, %1}, %2;" : "=f"(f.x), "=f"(f.y) : "l"(v));
    return f;
}
__device__ __forceinline__ float dot4(float4 a, float4 b) {
    return fmaf(a.x, b.x, a.y * b.y) + fmaf(a.z, b.z, a.w * b.w);
}

// ---- Kernel 1: fused projection GEMM (unchanged from round 4) ----
__global__ __launch_bounds__(256, 2)
void proj_gemm(const float* __restrict__ x,
               const float* __restrict__ Wk, const float* __restrict__ Wv,
               const float* __restrict__ Wq, const float* __restrict__ Wb)
{
    constexpr int BM = 128, BK = 16, LDA = 132;
    __shared__ __align__(16) float As[BK][LDA];
    __shared__ __align__(16) float Bs[BK][128];

    const int tid  = threadIdx.x;
    const int row0 = blockIdx.x * BM;
    const int bn   = blockIdx.y;

    const int a_r = tid >> 2;
    const int a_c = (tid & 3) * 4;
    const float* xA0 = x + (size_t)(row0 + a_r) * D_SZ + a_c;
    const float* xA1 = x + (size_t)(row0 + a_r + 64) * D_SZ + a_c;

    const int nl   = tid & 127;
    const int ncol = bn * 128 + nl;
    const float* Wm = (ncol < 64) ? Wk : (ncol < 128) ? Wv : (ncol < 192) ? Wq : Wb;
    const int b_c  = (tid >> 7) * 8;
    const float* wB = Wm + (size_t)(ncol & 63) * D_SZ + b_c;

    const int ty = tid >> 4;
    const int tx = tid & 15;

    unsigned long long acc[4][8];
    #pragma unroll
    for (int p = 0; p < 4; p++)
        #pragma unroll
        for (int j = 0; j < 8; j++) acc[p][j] = 0ULL;

    float4 ra0 = *(const float4*)(xA0);
    float4 ra1 = *(const float4*)(xA1);
    float4 rb0 = *(const float4*)(wB);
    float4 rb1 = *(const float4*)(wB + 4);

    for (int kt = 0; kt < D_SZ; kt += BK) {
        __syncthreads();
        As[a_c + 0][a_r] = ra0.x; As[a_c + 1][a_r] = ra0.y;
        As[a_c + 2][a_r] = ra0.z; As[a_c + 3][a_r] = ra0.w;
        As[a_c + 0][a_r + 64] = ra1.x; As[a_c + 1][a_r + 64] = ra1.y;
        As[a_c + 2][a_r + 64] = ra1.z; As[a_c + 3][a_r + 64] = ra1.w;
        Bs[b_c + 0][nl] = rb0.x; Bs[b_c + 1][nl] = rb0.y;
        Bs[b_c + 2][nl] = rb0.z; Bs[b_c + 3][nl] = rb0.w;
        Bs[b_c + 4][nl] = rb1.x; Bs[b_c + 5][nl] = rb1.y;
        Bs[b_c + 6][nl] = rb1.z; Bs[b_c + 7][nl] = rb1.w;
        __syncthreads();

        if (kt + BK < D_SZ) {
            ra0 = *(const float4*)(xA0 + kt + BK);
            ra1 = *(const float4*)(xA1 + kt + BK);
            rb0 = *(const float4*)(wB + kt + BK);
            rb1 = *(const float4*)(wB + kt + BK + 4);
        }

        #pragma unroll
        for (int kk = 0; kk < BK; kk++) {
            ulonglong2 aA = *(const ulonglong2*)&As[kk][ty * 8];
            ulonglong2 aB = *(const ulonglong2*)&As[kk][ty * 8 + 4];
            float4 b0 = *(const float4*)&Bs[kk][tx * 4];
            float4 b1 = *(const float4*)&Bs[kk][64 + tx * 4];
            unsigned long long bd[8];
            bd[0] = pk2(b0.x, b0.x); bd[1] = pk2(b0.y, b0.y);
            bd[2] = pk2(b0.z, b0.z); bd[3] = pk2(b0.w, b0.w);
            bd[4] = pk2(b1.x, b1.x); bd[5] = pk2(b1.y, b1.y);
            bd[6] = pk2(b1.z, b1.z); bd[7] = pk2(b1.w, b1.w);
            #pragma unroll
            for (int j = 0; j < 8; j++) {
                fma2(acc[0][j], aA.x, bd[j]);
                fma2(acc[1][j], aA.y, bd[j]);
                fma2(acc[2][j], aB.x, bd[j]);
                fma2(acc[3][j], aB.y, bd[j]);
            }
        }
    }

    const size_t c0 = (size_t)bn * 128 + tx * 4;
    #pragma unroll
    for (int p = 0; p < 4; p++) {
        float lo[8], hi[8];
        #pragma unroll
        for (int j = 0; j < 8; j++) { float2 f = unpk2(acc[p][j]); lo[j] = f.x; hi[j] = f.y; }
        size_t r = (size_t)(row0 + ty * 8 + 2 * p) * 256 + c0;
        *(float4*)&g_proj[r]            = make_float4(lo[0], lo[1], lo[2], lo[3]);
        *(float4*)&g_proj[r + 64]       = make_float4(lo[4], lo[5], lo[6], lo[7]);
        *(float4*)&g_proj[r + 256]      = make_float4(hi[0], hi[1], hi[2], hi[3]);
        *(float4*)&g_proj[r + 256 + 64] = make_float4(hi[4], hi[5], hi[6], hi[7]);
    }
}

// ---- Kernel 2: preprocess in place ----
__global__ __launch_bounds__(256)
void prep_kernel(const float* __restrict__ b_beta, int M)
{
    int w    = (blockIdx.x * 256 + threadIdx.x) >> 5;
    int lane = threadIdx.x & 31;
    if (w >= M) return;
    float* row = g_proj + (size_t)w * 256;

    float2 k2 = *(float2*)&row[lane * 2];
    float ss = k2.x * k2.x + k2.y * k2.y;
    #pragma unroll
    for (int o = 16; o > 0; o >>= 1) ss += __shfl_xor_sync(0xffffffffu, ss, o);
    float inv = 1.0f / (sqrtf(ss) + 1e-6f);
    k2.x *= inv; k2.y *= inv;
    *(float2*)&row[lane * 2] = k2;

    float2 b2 = *(float2*)&row[192 + lane * 2];
    float2 bb = *(const float2*)&b_beta[lane * 2];
    b2.x = 1.0f / (1.0f + expf(-(b2.x + bb.x)));
    b2.y = 1.0f / (1.0f + expf(-(b2.y + bb.y)));
    *(float2*)&row[192 + lane * 2] = b2;
}

// ---- Kernel 3: recurrence — 1 warp per SMSP across 128 SMs ----
__device__ __forceinline__ float tanh_fast(float x) {
    float e = __expf(2.0f * x);
    return 1.0f - __fdividef(2.0f, e + 1.0f);
}

__global__ __launch_bounds__(128)
void scan_kernel(const float* __restrict__ S0, float* __restrict__ out,
                 int T, long long out_elems)
{
    const int warp = threadIdx.x >> 5;               // 0..3
    const int lane = threadIdx.x & 31;
    const int half = lane >> 4;
    const int sl16 = lane & 15;
    const int gr   = (blockIdx.x * 4 + warp) * 2 + half;   // 0..1023
    const int b    = gr >> 6;
    const int i    = gr & 63;
    const int j0   = sl16 * 4;

    float4 s = *(const float4*)&S0[(size_t)b * 4096 + i * 64 + j0];

    const float* p = g_proj + (size_t)b * 256;
    float4 kn[4], q4[4], vk[4];
    float  bt[4];
    #pragma unroll
    for (int s4 = 0; s4 < 4; s4++) {
        const float* ps = p + (size_t)s4 * 4096;
        kn[s4] = __ldg((const float4*)&ps[j0]);
        q4[s4] = __ldg((const float4*)&ps[128 + j0]);
        float vv = __ldg(&ps[64 + i]);
        bt[s4]   = __ldg(&ps[192 + i]);
        vk[s4] = make_float4(vv * kn[s4].x, vv * kn[s4].y, vv * kn[s4].z, vv * kn[s4].w);
    }
    const float* pf = p + (size_t)4 * 4096;

    float rp = dot4(s, kn[0]);
    float4 pre = make_float4(fmaf(bt[0], s.x, vk[0].x), fmaf(bt[0], s.y, vk[0].y),
                             fmaf(bt[0], s.z, vk[0].z), fmaf(bt[0], s.w, vk[0].w));
    float sqp = 0.0f;

    const bool hasOut = ((long long)T * 1024 <= out_elems);
    const bool hasS   = ((long long)T * 1024 + (long long)B_SZ * 4096 <= out_elems);

    #pragma unroll 4
    for (int t = 0; t < T; t++) {
        const int cu = t & 3, nx = (t + 1) & 3;
        #pragma unroll
        for (int o = 8; o > 0; o >>= 1) {
            rp  += __shfl_xor_sync(0xffffffffu, rp,  o);
            sqp += __shfl_xor_sync(0xffffffffu, sqp, o);
        }
        s.x = tanh_fast(fmaf(-rp, kn[cu].x, pre.x));
        s.y = tanh_fast(fmaf(-rp, kn[cu].y, pre.y));
        s.z = tanh_fast(fmaf(-rp, kn[cu].z, pre.z));
        s.w = tanh_fast(fmaf(-rp, kn[cu].w, pre.w));
        if (t > 0 && sl16 == 0 && hasOut) {
            float sg = __fdividef(1.0f, 1.0f + __expf(-sqp));
            out[(size_t)(t - 1) * 1024 + b * 64 + i] = sqp * sqp * sg;
        }
        sqp = dot4(s, q4[cu]);
        rp  = dot4(s, kn[nx]);
        pre = make_float4(fmaf(bt[nx], s.x, vk[nx].x), fmaf(bt[nx], s.y, vk[nx].y),
                          fmaf(bt[nx], s.z, vk[nx].z), fmaf(bt[nx], s.w, vk[nx].w));
        kn[cu] = __ldg((const float4*)&pf[j0]);
        q4[cu] = __ldg((const float4*)&pf[128 + j0]);
        float vv = __ldg(&pf[64 + i]);
        bt[cu]   = __ldg(&pf[192 + i]);
        vk[cu] = make_float4(vv * kn[cu].x, vv * kn[cu].y, vv * kn[cu].z, vv * kn[cu].w);
        pf += 4096;
    }

    #pragma unroll
    for (int o = 8; o > 0; o >>= 1) sqp += __shfl_xor_sync(0xffffffffu, sqp, o);
    if (sl16 == 0 && hasOut) {
        float sg = __fdividef(1.0f, 1.0f + __expf(-sqp));
        out[(size_t)(T - 1) * 1024 + b * 64 + i] = sqp * sqp * sg;
    }
    if (hasS)
        *(float4*)&out[(size_t)T * 1024 + (size_t)b * 4096 + i * 64 + j0] = s;
}

// ---- host launcher ----
extern "C" void kernel_launch(void* const* d_in, const int* in_sizes, int n_in,
                              void* d_out, int out_size)
{
    const float* x  = (const float*)d_in[0];
    const float* S0 = (const float*)d_in[1];
    const float* Wk = (const float*)d_in[2];
    const float* Wv = (const float*)d_in[3];
    const float* Wq = (const float*)d_in[4];
    const float* Wb = (const float*)d_in[5];
    const float* bb = (const float*)d_in[6];

    dim3 g(M_ROWS / 128, 2);
    proj_gemm<<<g, 256>>>(x, Wk, Wv, Wq, Wb);
    prep_kernel<<<M_ROWS / 8, 256>>>(bb, M_ROWS);
    scan_kernel<<<128, 128>>>(S0, (float*)d_out, T_MAX, (long long)out_size);
}

// round 6
// speedup vs baseline: 1.4128x; 1.0411x over previous
#include <cuda_runtime.h>
#include <math.h>

#define T_MAX 2048
#define B_SZ  16
#define D_SZ  1024
#define M_ROWS (T_MAX * B_SZ)      // 32768
#define N_TILES 512                 // M_ROWS / 64 ; tile m = timesteps 4m..4m+3
#define SCAN_BLOCKS 64
#define GEMM_BLOCKS (N_TILES * 2)

// proj row m = t*16+b: [0:64)=k_norm, [64:128)=v, [128:192)=q, [192:256)=sigmoid(beta)
// +64 padded rows (never written -> stay zero) for the scan's lookahead.
__device__ __align__(16) float g_proj[(M_ROWS + 64) * 256];
__device__ int g_flag[N_TILES];

// ---- helpers ----
__device__ __forceinline__ unsigned long long pk2(float x, float y) {
    unsigned long long r;
    asm("mov.b64 %0, {%1, %2};" : "=l"(r) : "f"(x), "f"(y));
    return r;
}
__device__ __forceinline__ void fma2(unsigned long long& d, unsigned long long a, unsigned long long b) {
    asm("fma.rn.f32x2 %0, %1, %2, %0;" : "+l"(d) : "l"(a), "l"(b));
}
__device__ __forceinline__ float2 unpk2(unsigned long long v) {
    float2 f;
    asm("mov.b64 {%0, %1}, %2;" : "=f"(f.x), "=f"(f.y) : "l"(v));
    return f;
}
__device__ __forceinline__ float dot4(float4 a, float4 b) {
    return fmaf(a.x, b.x, a.y * b.y) + fmaf(a.z, b.z, a.w * b.w);
}
__device__ __forceinline__ int ld_acquire(const int* p) {
    int v;
    asm volatile("ld.acquire.gpu.global.b32 %0, [%1];" : "=r"(v) : "l"(p));
    return v;
}
__device__ __forceinline__ float tanh_fast(float x) {
    float e = __expf(2.0f * x);
    return 1.0f - __fdividef(2.0f, e + 1.0f);
}

__global__ void reset_kernel() { g_flag[threadIdx.x] = 0; }

// ---- fused producer (GEMM+prep) / consumer (scan) kernel ----
__global__ __launch_bounds__(256, 2)
void fused_kernel(const float* __restrict__ x,  const float* __restrict__ S0,
                  const float* __restrict__ Wk, const float* __restrict__ Wv,
                  const float* __restrict__ Wq, const float* __restrict__ Wb,
                  const float* __restrict__ bb, float* __restrict__ out,
                  long long out_elems)
{
    const int tid = threadIdx.x;

    if (blockIdx.x < SCAN_BLOCKS) {
        // ================= SCAN role =================
        const int warp = tid >> 5;               // 0..7
        const int lane = tid & 31;
        const int half = lane >> 4;
        const int sl16 = lane & 15;
        const int gr   = (blockIdx.x * 8 + warp) * 2 + half;  // 0..1023
        const int b    = gr >> 6;
        const int i    = gr & 63;
        const int j0   = sl16 * 4;
        const int T    = T_MAX;

        // wait tile 0 (steps 0..3)
        while (ld_acquire(&g_flag[0]) < 2) __nanosleep(256);

        float4 s = *(const float4*)&S0[(size_t)b * 4096 + i * 64 + j0];

        const float* p = g_proj + (size_t)b * 256;
        float4 kn[4], q4[4], vk[4];
        float  bt[4];
        #pragma unroll
        for (int s4 = 0; s4 < 4; s4++) {
            const float* ps = p + (size_t)s4 * 4096;
            kn[s4] = __ldg((const float4*)&ps[j0]);
            q4[s4] = __ldg((const float4*)&ps[128 + j0]);
            float vv = __ldg(&ps[64 + i]);
            bt[s4]   = __ldg(&ps[192 + i]);
            vk[s4] = make_float4(vv * kn[s4].x, vv * kn[s4].y, vv * kn[s4].z, vv * kn[s4].w);
        }
        const float* pf = p + (size_t)4 * 4096;

        float rp = dot4(s, kn[0]);
        float4 pre = make_float4(fmaf(bt[0], s.x, vk[0].x), fmaf(bt[0], s.y, vk[0].y),
                                 fmaf(bt[0], s.z, vk[0].z), fmaf(bt[0], s.w, vk[0].w));
        float sqp = 0.0f;

        const bool hasOut = ((long long)T * 1024 <= out_elems);
        const bool hasS   = ((long long)T * 1024 + (long long)B_SZ * 4096 <= out_elems);

        #pragma unroll 4
        for (int t = 0; t < T; t++) {
            if ((t & 15) == 0) {
                // gate refills for steps t+4..t+19 -> tiles (t>>2)+1 .. +4
                int base = (t >> 2) + 1;
                int ok;
                do {
                    ok = 1;
                    #pragma unroll
                    for (int f = 0; f < 4; f++) {
                        int tile = base + f;
                        if (tile < N_TILES) ok &= (ld_acquire(&g_flag[tile]) >= 2);
                    }
                    if (!ok) __nanosleep(256);
                } while (!ok);
            }
            const int cu = t & 3, nx = (t + 1) & 3;
            #pragma unroll
            for (int o = 8; o > 0; o >>= 1) {
                rp  += __shfl_xor_sync(0xffffffffu, rp,  o);
                sqp += __shfl_xor_sync(0xffffffffu, sqp, o);
            }
            s.x = tanh_fast(fmaf(-rp, kn[cu].x, pre.x));
            s.y = tanh_fast(fmaf(-rp, kn[cu].y, pre.y));
            s.z = tanh_fast(fmaf(-rp, kn[cu].z, pre.z));
            s.w = tanh_fast(fmaf(-rp, kn[cu].w, pre.w));
            if (t > 0 && sl16 == 0 && hasOut) {
                float sg = __fdividef(1.0f, 1.0f + __expf(-sqp));
                out[(size_t)(t - 1) * 1024 + b * 64 + i] = sqp * sqp * sg;
            }
            sqp = dot4(s, q4[cu]);
            rp  = dot4(s, kn[nx]);
            pre = make_float4(fmaf(bt[nx], s.x, vk[nx].x), fmaf(bt[nx], s.y, vk[nx].y),
                              fmaf(bt[nx], s.z, vk[nx].z), fmaf(bt[nx], s.w, vk[nx].w));
            kn[cu] = __ldg((const float4*)&pf[j0]);
            q4[cu] = __ldg((const float4*)&pf[128 + j0]);
            float vv = __ldg(&pf[64 + i]);
            bt[cu]   = __ldg(&pf[192 + i]);
            vk[cu] = make_float4(vv * kn[cu].x, vv * kn[cu].y, vv * kn[cu].z, vv * kn[cu].w);
            pf += 4096;
        }

        #pragma unroll
        for (int o = 8; o > 0; o >>= 1) sqp += __shfl_xor_sync(0xffffffffu, sqp, o);
        if (sl16 == 0 && hasOut) {
            float sg = __fdividef(1.0f, 1.0f + __expf(-sqp));
            out[(size_t)(T - 1) * 1024 + b * 64 + i] = sqp * sqp * sg;
        }
        if (hasS)
            *(float4*)&out[(size_t)T * 1024 + (size_t)b * 4096 + i * 64 + j0] = s;
        return;
    }

    // ================= GEMM + prep role (BM=64) =================
    {
        constexpr int BK = 16, LDA = 68;         // 272B rows, 16B-aligned
        __shared__ __align__(16) float As[BK][LDA];
        __shared__ __align__(16) float Bs[BK][128];

        const int g    = blockIdx.x - SCAN_BLOCKS;
        const int bm   = g >> 1;
        const int bn   = g & 1;                  // 0: k|v cols, 1: q|beta cols
        const int row0 = bm * 64;

        const int a_r = tid >> 2;                // 0..63
        const int a_c = (tid & 3) * 4;           // 0,4,8,12
        const float* xA = x + (size_t)(row0 + a_r) * D_SZ + a_c;

        const int nl   = tid & 127;
        const int ncol = bn * 128 + nl;
        const float* Wm = (ncol < 64) ? Wk : (ncol < 128) ? Wv : (ncol < 192) ? Wq : Wb;
        const int b_c  = (tid >> 7) * 8;
        const float* wB = Wm + (size_t)(ncol & 63) * D_SZ + b_c;

        const int ty = tid >> 4;                 // 0..15 -> 4 rows each (2 pairs)
        const int tx = tid & 15;                 // frag cols tx*4 and 64+tx*4

        unsigned long long acc[2][8];
        #pragma unroll
        for (int p = 0; p < 2; p++)
            #pragma unroll
            for (int j = 0; j < 8; j++) acc[p][j] = 0ULL;

        float4 ra  = *(const float4*)(xA);
        float4 rb0 = *(const float4*)(wB);
        float4 rb1 = *(const float4*)(wB + 4);

        for (int kt = 0; kt < D_SZ; kt += BK) {
            __syncthreads();
            As[a_c + 0][a_r] = ra.x; As[a_c + 1][a_r] = ra.y;
            As[a_c + 2][a_r] = ra.z; As[a_c + 3][a_r] = ra.w;
            Bs[b_c + 0][nl] = rb0.x; Bs[b_c + 1][nl] = rb0.y;
            Bs[b_c + 2][nl] = rb0.z; Bs[b_c + 3][nl] = rb0.w;
            Bs[b_c + 4][nl] = rb1.x; Bs[b_c + 5][nl] = rb1.y;
            Bs[b_c + 6][nl] = rb1.z; Bs[b_c + 7][nl] = rb1.w;
            __syncthreads();

            if (kt + BK < D_SZ) {
                ra  = *(const float4*)(xA + kt + BK);
                rb0 = *(const float4*)(wB + kt + BK);
                rb1 = *(const float4*)(wB + kt + BK + 4);
            }

            #pragma unroll
            for (int kk = 0; kk < BK; kk++) {
                ulonglong2 aP = *(const ulonglong2*)&As[kk][ty * 4];  // row pairs (0,1),(2,3)
                float4 b0 = *(const float4*)&Bs[kk][tx * 4];
                float4 b1 = *(const float4*)&Bs[kk][64 + tx * 4];
                unsigned long long bd[8];
                bd[0] = pk2(b0.x, b0.x); bd[1] = pk2(b0.y, b0.y);
                bd[2] = pk2(b0.z, b0.z); bd[3] = pk2(b0.w, b0.w);
                bd[4] = pk2(b1.x, b1.x); bd[5] = pk2(b1.y, b1.y);
                bd[6] = pk2(b1.z, b1.z); bd[7] = pk2(b1.w, b1.w);
                #pragma unroll
                for (int j = 0; j < 8; j++) {
                    fma2(acc[0][j], aP.x, bd[j]);
                    fma2(acc[1][j], aP.y, bd[j]);
                }
            }
        }

        // epilogue: unpack, apply prep, store
        float lo[2][8], hi[2][8];
        #pragma unroll
        for (int p = 0; p < 2; p++)
            #pragma unroll
            for (int j = 0; j < 8; j++) {
                float2 f = unpk2(acc[p][j]);
                lo[p][j] = f.x; hi[p][j] = f.y;
            }

        if (bn == 0) {
            // frag0 (j 0..3) = k cols tx*4..+3 -> normalize rows (16-lane reduce)
            #pragma unroll
            for (int p = 0; p < 2; p++) {
                float nlo = lo[p][0]*lo[p][0] + lo[p][1]*lo[p][1] + lo[p][2]*lo[p][2] + lo[p][3]*lo[p][3];
                float nhi = hi[p][0]*hi[p][0] + hi[p][1]*hi[p][1] + hi[p][2]*hi[p][2] + hi[p][3]*hi[p][3];
                #pragma unroll
                for (int o = 8; o > 0; o >>= 1) {
                    nlo += __shfl_xor_sync(0xffffffffu, nlo, o);
                    nhi += __shfl_xor_sync(0xffffffffu, nhi, o);
                }
                float ilo = 1.0f / (sqrtf(nlo) + 1e-6f);
                float ihi = 1.0f / (sqrtf(nhi) + 1e-6f);
                lo[p][0] *= ilo; lo[p][1] *= ilo; lo[p][2] *= ilo; lo[p][3] *= ilo;
                hi[p][0] *= ihi; hi[p][1] *= ihi; hi[p][2] *= ihi; hi[p][3] *= ihi;
            }
        } else {
            // frag1 (j 4..7) = beta cols 192+tx*4 -> sigmoid(v + b_beta)
            float4 bb4 = *(const float4*)&bb[tx * 4];
            #pragma unroll
            for (int p = 0; p < 2; p++) {
                lo[p][4] = 1.0f / (1.0f + expf(-(lo[p][4] + bb4.x)));
                lo[p][5] = 1.0f / (1.0f + expf(-(lo[p][5] + bb4.y)));
                lo[p][6] = 1.0f / (1.0f + expf(-(lo[p][6] + bb4.z)));
                lo[p][7] = 1.0f / (1.0f + expf(-(lo[p][7] + bb4.w)));
                hi[p][4] = 1.0f / (1.0f + expf(-(hi[p][4] + bb4.x)));
                hi[p][5] = 1.0f / (1.0f + expf(-(hi[p][5] + bb4.y)));
                hi[p][6] = 1.0f / (1.0f + expf(-(hi[p][6] + bb4.z)));
                hi[p][7] = 1.0f / (1.0f + expf(-(hi[p][7] + bb4.w)));
            }
        }

        const size_t c0 = (size_t)bn * 128 + tx * 4;
        #pragma unroll
        for (int p = 0; p < 2; p++) {
            size_t r = (size_t)(row0 + ty * 4 + 2 * p) * 256 + c0;
            *(float4*)&g_proj[r]            = make_float4(lo[p][0], lo[p][1], lo[p][2], lo[p][3]);
            *(float4*)&g_proj[r + 64]       = make_float4(lo[p][4], lo[p][5], lo[p][6], lo[p][7]);
            *(float4*)&g_proj[r + 256]      = make_float4(hi[p][0], hi[p][1], hi[p][2], hi[p][3]);
            *(float4*)&g_proj[r + 256 + 64] = make_float4(hi[p][4], hi[p][5], hi[p][6], hi[p][7]);
        }

        __syncthreads();
        if (tid == 0) {
            __threadfence();
            atomicAdd(&g_flag[bm], 1);   // tile ready when == 2 (both bn halves)
        }
    }
}

// ---- host launcher ----
extern "C" void kernel_launch(void* const* d_in, const int* in_sizes, int n_in,
                              void* d_out, int out_size)
{
    const float* x  = (const float*)d_in[0];
    const float* S0 = (const float*)d_in[1];
    const float* Wk = (const float*)d_in[2];
    const float* Wv = (const float*)d_in[3];
    const float* Wq = (const float*)d_in[4];
    const float* Wb = (const float*)d_in[5];
    const float* bb = (const float*)d_in[6];

    reset_kernel<<<1, N_TILES>>>();
    fused_kernel<<<SCAN_BLOCKS + GEMM_BLOCKS, 256>>>(
        x, S0, Wk, Wv, Wq, Wb, bb, (float*)d_out, (long long)out_size);
}